// round 3
// baseline (speedup 1.0000x reference)
#include <cuda_runtime.h>
#include <cstdint>

// Problem shapes (fixed by setup_inputs)
#define B      4
#define NC     1024
#define NF     8192

#define TILE   128          // rows per tile AND cols per unit
#define TPB    256          // 16x16 threads
#define NCTA   592          // 148 SMs x 4 CTAs: perfectly even residency
#define CHUNK  512          // rows per work unit
#define NUNITS (B * (NF / TILE) * (NF / CHUNK))   // 4*64*16 = 4096
#define NRED   148

#define INF_BITS 0x7f800000u
#define PADW   18

typedef unsigned long long u64;

// Scratch (allocation-free rule: __device__ globals)
__device__ unsigned int g_min1[B * NF];
__device__ unsigned int g_min2[B * NF];
__device__ float        g_part[NRED * 3];
__device__ unsigned int g_ticket;
__device__ unsigned int g_done;

// ---- packed f32x2 helpers (sm_103a) ---------------------------------------
__device__ __forceinline__ u64 pk(float lo, float hi) {
    u64 r; asm("mov.b64 %0, {%1, %2};" : "=l"(r) : "f"(lo), "f"(hi)); return r;
}
__device__ __forceinline__ void upk(float& lo, float& hi, u64 v) {
    asm("mov.b64 {%0, %1}, %2;" : "=f"(lo), "=f"(hi) : "l"(v));
}
__device__ __forceinline__ u64 fma2(u64 a, u64 b, u64 c) {
    u64 d; asm("fma.rn.f32x2 %0, %1, %2, %3;" : "=l"(d) : "l"(a), "l"(b), "l"(c)); return d;
}
__device__ __forceinline__ u64 add2(u64 a, u64 b) {
    u64 d; asm("add.rn.f32x2 %0, %1, %2;" : "=l"(d) : "l"(a), "l"(b)); return d;
}

// ---------------------------------------------------------------------------
__global__ void init_kernel() {
    int i = blockIdx.x * blockDim.x + threadIdx.x;
    if (i < B * NF) {
        g_min1[i] = INF_BITS;
        g_min2[i] = INF_BITS;
    }
    if (i == 0) { g_ticket = 0; g_done = 0; }
}

// ---------------------------------------------------------------------------
// Fused pairwise-distance + dual min-reduction, dynamic work queue.
// Unit = (b, colTile[128], rowChunk[512]).  X = ret_fine, Y = gt_fine.
__global__ __launch_bounds__(TPB, 4) void chamfer_kernel(const float* __restrict__ X,
                                                         const float* __restrict__ Y) {
    __shared__ ulonglong2   sXp[TILE][2];      // pre-packed row broadcast {x,x}{y,y} / {z,z}{w,w}
    __shared__ float        sPart[TILE][PADW]; // per-(row, tx) partial row mins  (also Y staging)
    __shared__ unsigned int sCol[TILE];
    __shared__ unsigned int sTicket;

    const int tid = threadIdx.x;
    const int tx  = tid & 15;
    const int ty  = tid >> 4;

    // persistent packed column regs for current col group
    u64 ya[4], yb[4], yc[4], yw[4];
    float cm[8];
    int   gid = -1;          // current col group: b*64 + colTile
    int   gb = 0, gcb = 0;   // its batch / col base

    for (;;) {
        if (tid == 0) sTicket = atomicAdd(&g_ticket, 1u);
        __syncthreads();
        const unsigned u = sTicket;
        if (u >= NUNITS) break;

        const int chunk = u & 15;
        const int ct    = (u >> 4) & 63;
        const int b     = (u >> 10) & 3;
        const int ng    = b * 64 + ct;

        if (ng != gid) {
            // flush col mins of previous group
            if (gid >= 0) {
                __syncthreads();
#pragma unroll
                for (int j = 0; j < 8; ++j)
                    atomicMin(&sCol[tx * 8 + j], __float_as_uint(fmaxf(cm[j], 0.0f)));
                __syncthreads();
                if (tid < TILE)
                    atomicMin(&g_min2[gb * NF + gcb + tid], sCol[tid]);
            }
            gid = ng; gb = b; gcb = ct * TILE;
            // stage Y tile (pre-scaled by -2, |y|^2 folded) through sPart storage
            float4* stage = (float4*)&sPart[0][0];
            __syncthreads();
            if (tid < TILE) {
                int jg = b * NF + gcb + tid;
                float y0 = Y[jg * 3 + 0];
                float y1 = Y[jg * 3 + 1];
                float y2 = Y[jg * 3 + 2];
                stage[tid] = make_float4(-2.0f * y0, -2.0f * y1, -2.0f * y2,
                                         fmaf(y0, y0, fmaf(y1, y1, y2 * y2)));
                sCol[tid] = INF_BITS;
            }
            __syncthreads();
#pragma unroll
            for (int g = 0; g < 4; ++g) {
                float4 p = stage[tx * 8 + 2 * g];
                float4 q = stage[tx * 8 + 2 * g + 1];
                ya[g] = pk(p.x, q.x);
                yb[g] = pk(p.y, q.y);
                yc[g] = pk(p.z, q.z);
                yw[g] = pk(p.w, q.w);
                cm[2 * g]     = __int_as_float(0x7f800000);
                cm[2 * g + 1] = __int_as_float(0x7f800000);
            }
            __syncthreads();
        }

        const int row0 = chunk * CHUNK;
#pragma unroll 1
        for (int t = 0; t < CHUNK / TILE; ++t) {
            const int r0 = row0 + t * TILE;
            if (tid < TILE) {
                int ig = b * NF + r0 + tid;
                float x0 = X[ig * 3 + 0];
                float x1 = X[ig * 3 + 1];
                float x2 = X[ig * 3 + 2];
                float w  = fmaf(x0, x0, fmaf(x1, x1, x2 * x2));
                sXp[tid][0] = make_ulonglong2(pk(x0, x0), pk(x1, x1));
                sXp[tid][1] = make_ulonglong2(pk(x2, x2), pk(w, w));
            }
            __syncthreads();   // sync A (also orders prev sPart reads vs new writes)

#pragma unroll
            for (int i = 0; i < 8; ++i) {
                const ulonglong2 qa = sXp[ty * 8 + i][0];
                const ulonglong2 qb = sXp[ty * 8 + i][1];
                float rml = __int_as_float(0x7f800000);
                float rmh = __int_as_float(0x7f800000);
#pragma unroll
                for (int g = 0; g < 4; ++g) {
                    u64 e = add2(yw[g], qb.y);     // |x|^2 + |y|^2
                    e = fma2(yc[g], qb.x, e);      // -2 z.z
                    e = fma2(yb[g], qa.y, e);      // -2 y.y
                    e = fma2(ya[g], qa.x, e);      // -2 x.x
                    float dl, dh;
                    upk(dl, dh, e);
                    rml = fminf(rml, dl);
                    rmh = fminf(rmh, dh);
                    cm[2 * g]     = fminf(cm[2 * g],     dl);
                    cm[2 * g + 1] = fminf(cm[2 * g + 1], dh);
                }
                sPart[ty * 8 + i][tx] = fminf(rml, rmh);
            }
            __syncthreads();   // sync B

            if (tid < TILE) {
                float m = sPart[tid][0];
#pragma unroll
                for (int c = 1; c < 16; ++c) m = fminf(m, sPart[tid][c]);
                atomicMin(&g_min1[b * NF + r0 + tid], __float_as_uint(fmaxf(m, 0.0f)));
            }
        }
        __syncthreads();   // orders sPart/sTicket reuse across units
    }

    // flush last group
    if (gid >= 0) {
        __syncthreads();
#pragma unroll
        for (int j = 0; j < 8; ++j)
            atomicMin(&sCol[tx * 8 + j], __float_as_uint(fmaxf(cm[j], 0.0f)));
        __syncthreads();
        if (tid < TILE)
            atomicMin(&g_min2[gb * NF + gcb + tid], sCol[tid]);
    }
}

// ---------------------------------------------------------------------------
// Partial sums (sqrt of min arrays + coarse L2) with fused last-block final.
__global__ __launch_bounds__(TPB) void reduce_kernel(const float* __restrict__ rc,
                                                     const float* __restrict__ gc,
                                                     float* __restrict__ out) {
    __shared__ float sbuf[TPB];
    __shared__ bool  sLast;
    const int tid    = threadIdx.x;
    const int gstart = blockIdx.x * TPB + tid;
    const int stride = gridDim.x * TPB;

    float s1 = 0.0f, s2 = 0.0f, sc = 0.0f;
    for (int i = gstart; i < B * NF; i += stride)
        s1 += sqrtf(__uint_as_float(g_min1[i]));
    for (int i = gstart; i < B * NF; i += stride)
        s2 += sqrtf(__uint_as_float(g_min2[i]));
    for (int p = gstart; p < B * NC; p += stride) {
        float d0 = rc[p * 3 + 0] - gc[p * 3 + 0];
        float d1 = rc[p * 3 + 1] - gc[p * 3 + 1];
        float d2 = rc[p * 3 + 2] - gc[p * 3 + 2];
        sc += sqrtf(fmaf(d0, d0, fmaf(d1, d1, d2 * d2)));
    }

    float vals[3] = {s1, s2, sc};
#pragma unroll
    for (int k = 0; k < 3; ++k) {
        sbuf[tid] = vals[k];
        __syncthreads();
        for (int off = TPB / 2; off > 0; off >>= 1) {
            if (tid < off) sbuf[tid] += sbuf[tid + off];
            __syncthreads();
        }
        if (tid == 0) g_part[blockIdx.x * 3 + k] = sbuf[0];
        __syncthreads();
    }

    // last block combines (deterministic: fixed array, fixed order)
    __threadfence();
    if (tid == 0) sLast = (atomicAdd(&g_done, 1u) == gridDim.x - 1);
    __syncthreads();
    if (!sLast) return;

    float r1 = 0.0f, r2 = 0.0f, r3 = 0.0f;
    for (int c = tid; c < NRED; c += TPB) {
        r1 += g_part[c * 3 + 0];
        r2 += g_part[c * 3 + 1];
        r3 += g_part[c * 3 + 2];
    }
    float v2[3] = {r1, r2, r3};
    float acc[3];
#pragma unroll
    for (int k = 0; k < 3; ++k) {
        sbuf[tid] = v2[k];
        __syncthreads();
        for (int off = TPB / 2; off > 0; off >>= 1) {
            if (tid < off) sbuf[tid] += sbuf[tid + off];
            __syncthreads();
        }
        acc[k] = sbuf[0];
        __syncthreads();
    }
    if (tid == 0) {
        const float invBN = 1.0f / (float)(B * NF);
        out[0] = acc[2] / (float)(B * NC);                   // loss_coarse
        out[1] = 0.5f * (acc[0] * invBN + acc[1] * invBN);   // loss_fine
    }
}

// ---------------------------------------------------------------------------
extern "C" void kernel_launch(void* const* d_in, const int* in_sizes, int n_in,
                              void* d_out, int out_size) {
    const float* ret_coarse = (const float*)d_in[0];
    const float* ret_fine   = (const float*)d_in[1];
    const float* gt_fine    = (const float*)d_in[2];
    const float* gt_coarse  = (const float*)d_in[3];
    float* out = (float*)d_out;

    init_kernel<<<(B * NF + TPB - 1) / TPB, TPB>>>();
    chamfer_kernel<<<NCTA, TPB>>>(ret_fine, gt_fine);
    reduce_kernel<<<NRED, TPB>>>(ret_coarse, gt_coarse, out);
}

// round 4
// speedup vs baseline: 2.4020x; 2.4020x over previous
#include <cuda_runtime.h>
#include <cstdint>

// Problem shapes (fixed by setup_inputs)
#define B      4
#define NC     1024
#define NF     8192

#define TILE     128        // rows per tile AND cols per CTA
#define TPB      256        // 16x16 threads
#define ROWSPLIT 8          // CTAs splitting the row dimension
#define NCT      (NF / TILE)            // 64 col tiles
#define BNF      (B * NF)               // 32768
#define NRED     148

#define PADW   18           // sPart row pad -> conflict-free STS

typedef unsigned long long u64;

// Scratch (allocation-free rule: __device__ globals). No atomics, no init:
// every slot is written exactly once per launch.
__device__ float g_rowpart[NCT * BNF];       // [colTile][b*NF + row]  (8 MB)
__device__ float g_colpart[ROWSPLIT * BNF];  // [rowSplit][b*NF + col] (1 MB)
__device__ float g_part[NRED * 3];
__device__ unsigned int g_done;              // self-resetting -> graph-replay safe

// ---- packed f32x2 helpers (sm_103a) ---------------------------------------
__device__ __forceinline__ u64 pk(float lo, float hi) {
    u64 r; asm("mov.b64 %0, {%1, %2};" : "=l"(r) : "f"(lo), "f"(hi)); return r;
}
__device__ __forceinline__ void upk(float& lo, float& hi, u64 v) {
    asm("mov.b64 {%0, %1}, %2;" : "=f"(lo), "=f"(hi) : "l"(v));
}
__device__ __forceinline__ u64 fma2(u64 a, u64 b, u64 c) {
    u64 d; asm("fma.rn.f32x2 %0, %1, %2, %3;" : "=l"(d) : "l"(a), "l"(b), "l"(c)); return d;
}
__device__ __forceinline__ u64 add2(u64 a, u64 b) {
    u64 d; asm("add.rn.f32x2 %0, %1, %2;" : "=l"(d) : "l"(a), "l"(b)); return d;
}

// ---------------------------------------------------------------------------
// Fused pairwise-distance + dual min-reduction. Static grid, private partials.
// grid: (NCT, ROWSPLIT, B), block 16x16, micro-tile 8x8 (cols packed 2-wide).
// X = ret_fine (rows -> g_rowpart), Y = gt_fine (cols -> g_colpart).
__global__ __launch_bounds__(TPB, 4) void chamfer_kernel(const float* __restrict__ X,
                                                         const float* __restrict__ Y) {
    __shared__ ulonglong2   sXp[TILE][2];      // pre-packed rows {x,x}{y,y} / {z,z}{w,w}
    __shared__ float        sPart[TILE][PADW]; // per-(row, tx) partial row mins (Y staging 1st)
    __shared__ unsigned int sCol[TILE];

    const int tid = threadIdx.x;
    const int tx  = tid & 15;              // 16 col-thread groups (8 cols each)
    const int ty  = tid >> 4;              // 16 row-thread groups (8 rows each)
    const int b   = blockIdx.z;
    const int ct  = blockIdx.x;
    const int ry  = blockIdx.y;
    const int colbase = ct * TILE;
    const int row0    = ry * (NF / ROWSPLIT);
    const int nTiles  = (NF / ROWSPLIT) / TILE;   // 8

    // Stage Y tile through sPart storage: (-2x, -2y, -2z, |y|^2)
    float4* stage = (float4*)&sPart[0][0];
    if (tid < TILE) {
        int jg = b * NF + colbase + tid;
        float y0 = Y[jg * 3 + 0];
        float y1 = Y[jg * 3 + 1];
        float y2 = Y[jg * 3 + 2];
        stage[tid] = make_float4(-2.0f * y0, -2.0f * y1, -2.0f * y2,
                                 fmaf(y0, y0, fmaf(y1, y1, y2 * y2)));
        sCol[tid] = 0x7f800000u;
    }
    __syncthreads();

    // Persistent packed column registers: 8 cols as 4 f32x2 groups
    u64 ya[4], yb[4], yc[4], yw[4];
    float cm[8];
#pragma unroll
    for (int g = 0; g < 4; ++g) {
        float4 p = stage[tx * 8 + 2 * g];
        float4 q = stage[tx * 8 + 2 * g + 1];
        ya[g] = pk(p.x, q.x);
        yb[g] = pk(p.y, q.y);
        yc[g] = pk(p.z, q.z);
        yw[g] = pk(p.w, q.w);
        cm[2 * g]     = __int_as_float(0x7f800000);
        cm[2 * g + 1] = __int_as_float(0x7f800000);
    }
    __syncthreads();   // done staging Y through sPart

    for (int t = 0; t < nTiles; ++t) {
        const int r0 = row0 + t * TILE;
        if (tid < TILE) {
            int ig = b * NF + r0 + tid;
            float x0 = X[ig * 3 + 0];
            float x1 = X[ig * 3 + 1];
            float x2 = X[ig * 3 + 2];
            float w  = fmaf(x0, x0, fmaf(x1, x1, x2 * x2));
            sXp[tid][0] = make_ulonglong2(pk(x0, x0), pk(x1, x1));
            sXp[tid][1] = make_ulonglong2(pk(x2, x2), pk(w, w));
        }
        __syncthreads();   // sync A

#pragma unroll
        for (int i = 0; i < 8; ++i) {
            const ulonglong2 qa = sXp[ty * 8 + i][0];   // {x,x},{y,y}
            const ulonglong2 qb = sXp[ty * 8 + i][1];   // {z,z},{w,w}
            float rml = __int_as_float(0x7f800000);
            float rmh = __int_as_float(0x7f800000);
#pragma unroll
            for (int g = 0; g < 4; ++g) {
                // d = |x|^2 + |y|^2 - 2 x.y   (y pre-scaled by -2, |y|^2 folded)
                u64 e = add2(yw[g], qb.y);
                e = fma2(yc[g], qb.x, e);
                e = fma2(yb[g], qa.y, e);
                e = fma2(ya[g], qa.x, e);
                float dl, dh;
                upk(dl, dh, e);
                rml = fminf(rml, dl);
                rmh = fminf(rmh, dh);
                cm[2 * g]     = fminf(cm[2 * g],     dl);
                cm[2 * g + 1] = fminf(cm[2 * g + 1], dh);
            }
            sPart[ty * 8 + i][tx] = fminf(rml, rmh);
        }
        __syncthreads();   // sync B

        if (tid < TILE) {
            float m = sPart[tid][0];
#pragma unroll
            for (int c = 1; c < 16; ++c) m = fminf(m, sPart[tid][c]);
            g_rowpart[ct * BNF + b * NF + r0 + tid] = m;   // plain store, written once
        }
        // loop-top sync A orders sPart rewrite after these reads
    }

    // Flush column mins once per CTA (smem atomics only)
#pragma unroll
    for (int j = 0; j < 8; ++j)
        atomicMin(&sCol[tx * 8 + j], __float_as_uint(fmaxf(cm[j], 0.0f)));
    __syncthreads();
    if (tid < TILE)
        g_colpart[ry * BNF + b * NF + colbase + tid] = __uint_as_float(sCol[tid]);
}

// ---------------------------------------------------------------------------
// Fold partial mins, sqrt, sum; last block combines and writes the outputs.
__global__ __launch_bounds__(TPB) void reduce_kernel(const float* __restrict__ rc,
                                                     const float* __restrict__ gc,
                                                     float* __restrict__ out) {
    __shared__ float sbuf[TPB];
    __shared__ bool  sLast;
    const int tid    = threadIdx.x;
    const int gstart = blockIdx.x * TPB + tid;
    const int stride = gridDim.x * TPB;

    float s1 = 0.0f, s2 = 0.0f, sc = 0.0f;
    for (int i = gstart; i < BNF; i += stride) {
        float m = g_rowpart[i];
#pragma unroll 8
        for (int ctl = 1; ctl < NCT; ++ctl)
            m = fminf(m, g_rowpart[ctl * BNF + i]);
        s1 += sqrtf(fmaxf(m, 0.0f));
    }
    for (int i = gstart; i < BNF; i += stride) {
        float m = g_colpart[i];
#pragma unroll
        for (int r = 1; r < ROWSPLIT; ++r)
            m = fminf(m, g_colpart[r * BNF + i]);
        s2 += sqrtf(m);   // already clamped >= 0
    }
    for (int p = gstart; p < B * NC; p += stride) {
        float d0 = rc[p * 3 + 0] - gc[p * 3 + 0];
        float d1 = rc[p * 3 + 1] - gc[p * 3 + 1];
        float d2 = rc[p * 3 + 2] - gc[p * 3 + 2];
        sc += sqrtf(fmaf(d0, d0, fmaf(d1, d1, d2 * d2)));
    }

    float vals[3] = {s1, s2, sc};
#pragma unroll
    for (int k = 0; k < 3; ++k) {
        sbuf[tid] = vals[k];
        __syncthreads();
        for (int off = TPB / 2; off > 0; off >>= 1) {
            if (tid < off) sbuf[tid] += sbuf[tid + off];
            __syncthreads();
        }
        if (tid == 0) g_part[blockIdx.x * 3 + k] = sbuf[0];
        __syncthreads();
    }

    // Last block combines (deterministic fixed order), then resets g_done
    // so the next graph replay starts from 0.
    __threadfence();
    if (tid == 0) sLast = (atomicAdd(&g_done, 1u) == gridDim.x - 1);
    __syncthreads();
    if (!sLast) return;

    float r1 = 0.0f, r2 = 0.0f, r3 = 0.0f;
    for (int c = tid; c < NRED; c += TPB) {
        r1 += g_part[c * 3 + 0];
        r2 += g_part[c * 3 + 1];
        r3 += g_part[c * 3 + 2];
    }
    float v2[3] = {r1, r2, r3};
    float acc[3];
#pragma unroll
    for (int k = 0; k < 3; ++k) {
        sbuf[tid] = v2[k];
        __syncthreads();
        for (int off = TPB / 2; off > 0; off >>= 1) {
            if (tid < off) sbuf[tid] += sbuf[tid + off];
            __syncthreads();
        }
        acc[k] = sbuf[0];
        __syncthreads();
    }
    if (tid == 0) {
        const float invBN = 1.0f / (float)(B * NF);
        out[0] = acc[2] / (float)(B * NC);                   // loss_coarse
        out[1] = 0.5f * (acc[0] * invBN + acc[1] * invBN);   // loss_fine
        g_done = 0;                                          // reset for next replay
    }
}

// ---------------------------------------------------------------------------
extern "C" void kernel_launch(void* const* d_in, const int* in_sizes, int n_in,
                              void* d_out, int out_size) {
    const float* ret_coarse = (const float*)d_in[0];
    const float* ret_fine   = (const float*)d_in[1];
    const float* gt_fine    = (const float*)d_in[2];
    const float* gt_coarse  = (const float*)d_in[3];
    float* out = (float*)d_out;

    dim3 grid(NCT, ROWSPLIT, B);   // (64, 8, 4) = 2048 CTAs x 8 tiles
    chamfer_kernel<<<grid, TPB>>>(ret_fine, gt_fine);
    reduce_kernel<<<NRED, TPB>>>(ret_coarse, gt_coarse, out);
}